// round 8
// baseline (speedup 1.0000x reference)
#include <cuda_runtime.h>
#include <cuda_bf16.h>
#include <math.h>
#include <stdint.h>

// Problem constants
#define BB 128
#define TT 512
#define DD 512
#define HH 512
#define G4 2048
#define NR (BB*TT)
#define AA 32

typedef __nv_bfloat16 bf16;

// ---------------- scratch (device globals) ----------------
__device__ float g_Gpi[(size_t)NR * G4];
__device__ float g_Gvf[(size_t)NR * G4];
__device__ float g_Z2pi[(size_t)NR * HH];
__device__ float g_Z2vf[(size_t)NR * HH];
__device__ volatile unsigned g_hflag[128];   // monotonic per-CTA progress flags

// bf16 hi/lo pairs
__device__ __align__(16) bf16 g_feat_h[(size_t)NR * DD];
__device__ __align__(16) bf16 g_feat_l[(size_t)NR * DD];
__device__ __align__(16) bf16 g_ypi_h[(size_t)NR * HH];
__device__ __align__(16) bf16 g_ypi_l[(size_t)NR * HH];
__device__ __align__(16) bf16 g_yvf_h[(size_t)NR * HH];
__device__ __align__(16) bf16 g_yvf_l[(size_t)NR * HH];
__device__ __align__(16) bf16 g_z1p_h[(size_t)NR * HH];
__device__ __align__(16) bf16 g_z1p_l[(size_t)NR * HH];
__device__ __align__(16) bf16 g_z1v_h[(size_t)NR * HH];
__device__ __align__(16) bf16 g_z1v_l[(size_t)NR * HH];
// h ping-pong: [lstm][pingpong][128][512], bf16 hi/lo (pre-masked for the consuming step)
__device__ __align__(16) bf16 g_hh[2 * 2 * BB * HH];
__device__ __align__(16) bf16 g_hl[2 * 2 * BB * HH];
// weights blob
#define WOFF_IHPI 0
#define WOFF_IHVF 1048576
#define WOFF_PW1  2097152
#define WOFF_PW2  2359296
#define WOFF_VW1  2621440
#define WOFF_VW2  2883584
#define WTOT      3145728
__device__ __align__(16) bf16 g_w_h[WTOT];
__device__ __align__(16) bf16 g_w_l[WTOT];

__device__ __forceinline__ float sigf(float x) { return 1.0f / (1.0f + __expf(-x)); }

// ---------------- PTX helpers ----------------
#define CP16(d, s) asm volatile("cp.async.cg.shared.global [%0], [%1], 16;" :: "r"(d), "l"(s) : "memory")
#define CP_COMMIT() asm volatile("cp.async.commit_group;" ::: "memory")
#define CP_WAIT0()  asm volatile("cp.async.wait_group 0;" ::: "memory")
#define CP_WAIT1()  asm volatile("cp.async.wait_group 1;" ::: "memory")

__device__ __forceinline__ uint32_t smem_u32(const void* p) {
    uint32_t a;
    asm("{ .reg .u64 t; cvta.to.shared.u64 t, %1; cvt.u32.u64 %0, t; }" : "=r"(a) : "l"(p));
    return a;
}

#define MMA16816(c, a, b) \
    asm volatile("mma.sync.aligned.m16n8k16.row.col.f32.bf16.bf16.f32 " \
        "{%0,%1,%2,%3}, {%4,%5,%6,%7}, {%8,%9}, {%0,%1,%2,%3};" \
        : "+f"((c)[0]), "+f"((c)[1]), "+f"((c)[2]), "+f"((c)[3]) \
        : "r"((a)[0]), "r"((a)[1]), "r"((a)[2]), "r"((a)[3]), "r"((b)[0]), "r"((b)[1]))

// ---------------- fp32 -> bf16 hi/lo converter ----------------
__global__ __launch_bounds__(256) void cvt_pair(const float* __restrict__ x,
                                                bf16* __restrict__ hi, bf16* __restrict__ lo, size_t n4)
{
    for (size_t i = blockIdx.x * blockDim.x + threadIdx.x; i < n4; i += (size_t)gridDim.x * blockDim.x) {
        float4 v = ((const float4*)x)[i];
        bf16 h0 = __float2bfloat16_rn(v.x), h1 = __float2bfloat16_rn(v.y);
        bf16 h2 = __float2bfloat16_rn(v.z), h3 = __float2bfloat16_rn(v.w);
        bf16 l0 = __float2bfloat16_rn(v.x - __bfloat162float(h0));
        bf16 l1 = __float2bfloat16_rn(v.y - __bfloat162float(h1));
        bf16 l2 = __float2bfloat16_rn(v.z - __bfloat162float(h2));
        bf16 l3 = __float2bfloat16_rn(v.w - __bfloat162float(h3));
        __nv_bfloat162 hp0; hp0.x = h0; hp0.y = h1;
        __nv_bfloat162 hp1; hp1.x = h2; hp1.y = h3;
        __nv_bfloat162 lp0; lp0.x = l0; lp0.y = l1;
        __nv_bfloat162 lp1; lp1.x = l2; lp1.y = l3;
        ((__nv_bfloat162*)hi)[2 * i]     = hp0;
        ((__nv_bfloat162*)hi)[2 * i + 1] = hp1;
        ((__nv_bfloat162*)lo)[2 * i]     = lp0;
        ((__nv_bfloat162*)lo)[2 * i + 1] = lp1;
    }
}

// ---------------- HMMA bf16-split GEMM (unchanged) ----------------
#define KSTG 32
#define ROWP 40
#define MATB (128 * ROWP)
#define STGB (4 * MATB)
__global__ __launch_bounds__(256, 1) void tgemm(
    const bf16* __restrict__ Ah, const bf16* __restrict__ Al,
    const bf16* __restrict__ Wh, const bf16* __restrict__ Wl,
    const float* __restrict__ b1, const float* __restrict__ b2,
    float* __restrict__ C, bf16* __restrict__ Ch, bf16* __restrict__ Cl,
    int N, int relu)
{
    extern __shared__ bf16 smbf[];
    const int tid  = threadIdx.x;
    const int wid  = tid >> 5, lane = tid & 31;
    const int g    = lane >> 2, tig = lane & 3;
    const int m0   = (wid & 3) * 32;
    const int n0   = (wid >> 2) * 64;
    const size_t arow0 = (size_t)blockIdx.y * 128;
    const size_t brow0 = (size_t)blockIdx.x * 128;

    const int lmat = tid >> 6, t64 = tid & 63;
    const bf16* gsrc;
    if      (lmat == 0) gsrc = Ah + arow0 * 512;
    else if (lmat == 1) gsrc = Al + arow0 * 512;
    else if (lmat == 2) gsrc = Wh + brow0 * 512;
    else                gsrc = Wl + brow0 * 512;
    const uint32_t sbase = smem_u32(smbf);
    const uint32_t sdstm = sbase + (uint32_t)lmat * (MATB * 2);

    float acc[2][8][4];
#pragma unroll
    for (int i = 0; i < 2; i++)
#pragma unroll
        for (int j = 0; j < 8; j++)
#pragma unroll
            for (int q = 0; q < 4; q++) acc[i][j][q] = 0.0f;

#pragma unroll
    for (int s = 0; s < 2; s++) {
        const uint32_t db = sdstm + (uint32_t)s * (STGB * 2);
        const int k0 = s * KSTG;
#pragma unroll
        for (int i = 0; i < 8; i++) {
            int idx = i * 64 + t64;
            int row = idx >> 2, gg = idx & 3;
            CP16(db + (uint32_t)row * (ROWP * 2) + (uint32_t)gg * 16,
                 gsrc + (size_t)row * 512 + k0 + gg * 8);
        }
        CP_COMMIT();
    }

    const int NSTG = 512 / KSTG;
#pragma unroll 1
    for (int c = 0; c < NSTG; c++) {
        if (c < NSTG - 2) { CP_WAIT1(); } else { CP_WAIT0(); }
        __syncthreads();
        const bf16* S   = smbf + (size_t)(c & 1) * STGB;
        const bf16* sAh = S;
        const bf16* sAl = S + MATB;
        const bf16* sWh = S + 2 * MATB;
        const bf16* sWl = S + 3 * MATB;
#pragma unroll
        for (int kk = 0; kk < KSTG; kk += 16) {
            uint32_t ah[2][4], al[2][4];
#pragma unroll
            for (int tm = 0; tm < 2; tm++) {
                const bf16* p = sAh + (m0 + tm * 16 + g) * ROWP + kk + 2 * tig;
                ah[tm][0] = *(const uint32_t*)(p);
                ah[tm][1] = *(const uint32_t*)(p + 8 * ROWP);
                ah[tm][2] = *(const uint32_t*)(p + 8);
                ah[tm][3] = *(const uint32_t*)(p + 8 * ROWP + 8);
                const bf16* q = sAl + (m0 + tm * 16 + g) * ROWP + kk + 2 * tig;
                al[tm][0] = *(const uint32_t*)(q);
                al[tm][1] = *(const uint32_t*)(q + 8 * ROWP);
                al[tm][2] = *(const uint32_t*)(q + 8);
                al[tm][3] = *(const uint32_t*)(q + 8 * ROWP + 8);
            }
            uint32_t bh[8][2], bl[8][2];
#pragma unroll
            for (int tn = 0; tn < 8; tn++) {
                const bf16* p = sWh + (n0 + tn * 8 + g) * ROWP + kk + 2 * tig;
                bh[tn][0] = *(const uint32_t*)(p);
                bh[tn][1] = *(const uint32_t*)(p + 8);
                const bf16* q = sWl + (n0 + tn * 8 + g) * ROWP + kk + 2 * tig;
                bl[tn][0] = *(const uint32_t*)(q);
                bl[tn][1] = *(const uint32_t*)(q + 8);
            }
#pragma unroll
            for (int tm = 0; tm < 2; tm++)
#pragma unroll
                for (int tn = 0; tn < 8; tn++) {
                    MMA16816(acc[tm][tn], ah[tm], bh[tn]);
                    MMA16816(acc[tm][tn], ah[tm], bl[tn]);
                    MMA16816(acc[tm][tn], al[tm], bh[tn]);
                }
        }
        __syncthreads();
        if (c + 2 < NSTG) {
            const uint32_t db = sdstm + (uint32_t)(c & 1) * (STGB * 2);
            const int k0 = (c + 2) * KSTG;
#pragma unroll
            for (int i = 0; i < 8; i++) {
                int idx = i * 64 + t64;
                int row = idx >> 2, gg = idx & 3;
                CP16(db + (uint32_t)row * (ROWP * 2) + (uint32_t)gg * 16,
                     gsrc + (size_t)row * 512 + k0 + gg * 8);
            }
            CP_COMMIT();
        }
    }

#pragma unroll
    for (int tn = 0; tn < 8; tn++) {
        int cc = (int)brow0 + n0 + tn * 8 + 2 * tig;
        float bv0 = b1[cc]     + (b2 ? b2[cc]     : 0.0f);
        float bv1 = b1[cc + 1] + (b2 ? b2[cc + 1] : 0.0f);
#pragma unroll
        for (int tm = 0; tm < 2; tm++) {
            size_t r0 = arow0 + m0 + tm * 16 + g;
            float v[4];
            v[0] = acc[tm][tn][0] + bv0;
            v[1] = acc[tm][tn][1] + bv1;
            v[2] = acc[tm][tn][2] + bv0;
            v[3] = acc[tm][tn][3] + bv1;
            if (relu) {
#pragma unroll
                for (int q = 0; q < 4; q++) v[q] = fmaxf(v[q], 0.f);
            }
            if (Ch) {
                __nv_bfloat162 h0, h1, l0, l1;
                h0.x = __float2bfloat16_rn(v[0]); h0.y = __float2bfloat16_rn(v[1]);
                h1.x = __float2bfloat16_rn(v[2]); h1.y = __float2bfloat16_rn(v[3]);
                l0.x = __float2bfloat16_rn(v[0] - __bfloat162float(h0.x));
                l0.y = __float2bfloat16_rn(v[1] - __bfloat162float(h0.y));
                l1.x = __float2bfloat16_rn(v[2] - __bfloat162float(h1.x));
                l1.y = __float2bfloat16_rn(v[3] - __bfloat162float(h1.y));
                *(__nv_bfloat162*)(Ch + r0 * (size_t)N + cc)       = h0;
                *(__nv_bfloat162*)(Cl + r0 * (size_t)N + cc)       = l0;
                *(__nv_bfloat162*)(Ch + (r0 + 8) * (size_t)N + cc) = h1;
                *(__nv_bfloat162*)(Cl + (r0 + 8) * (size_t)N + cc) = l1;
            } else {
                *(float2*)(C + r0 * (size_t)N + cc)       = make_float2(v[0], v[1]);
                *(float2*)(C + (r0 + 8) * (size_t)N + cc) = make_float2(v[2], v[3]);
            }
        }
    }
}

// ---------------- persistent recurrent kernel: flag-pipelined HMMA ----------------
// 128 CTAs x 256 thr. ct: lstm=ct>>6, batch-half b0, cid=ct&31 -> 16 h-cols / 64 gate-cols.
// No grid barrier: per-CTA monotonic flags; chunk c (128 h-cols) polls its 8 producer CTAs.
#define RPAD 136
#define WPAD 520
#define SGPAD 72
#define HMAT (64 * RPAD * 2)
#define OFF_WH   0
#define OFF_WL   (64 * WPAD * 2)
#define OFF_HH0  (2 * 64 * WPAD * 2)
#define OFF_HH1  (OFF_HH0 + HMAT)
#define OFF_HL0  (OFF_HH0 + 2 * HMAT)
#define OFF_HL1  (OFF_HL0 + HMAT)
#define OFF_SG   (OFF_HH0 + 4 * HMAT)
#define OFF_SC   (OFF_SG + 64 * SGPAD * 4)
#define LSTM_SMEM (OFF_SC + 64 * 16 * 4)

__global__ __launch_bounds__(256, 1) void lstm_recur(
    const float* __restrict__ Gpi, const float* __restrict__ Gvf,
    const float* __restrict__ starts,
    const float* __restrict__ h0pi, const float* __restrict__ c0pi,
    const float* __restrict__ h0vf, const float* __restrict__ c0vf,
    const float* __restrict__ Whhpi, const float* __restrict__ Whhvf,
    bf16* __restrict__ Yph, bf16* __restrict__ Ypl,
    bf16* __restrict__ Yvh, bf16* __restrict__ Yvl,
    bf16* __restrict__ hhg, bf16* __restrict__ hlg,
    float* __restrict__ out)
{
    extern __shared__ char sm8[];
    bf16*  sWh = (bf16*)(sm8 + OFF_WH);
    bf16*  sWl = (bf16*)(sm8 + OFF_WL);
    float* sg  = (float*)(sm8 + OFF_SG);
    float* sc  = (float*)(sm8 + OFF_SC);

    const int ct   = blockIdx.x;
    const int lstm = ct >> 6;
    const int gbase = ct & ~31;          // group base (32 CTAs)
    const int b0   = ((ct >> 5) & 1) * 64;
    const int cid  = ct & 31;
    const int hc0  = cid * 16;
    const int tx   = threadIdx.x;
    const int wid  = tx >> 5, lane = tx & 31;
    const int g    = lane >> 2, tig = lane & 3;
    const int m0w  = (wid & 1) * 32;
    const int n0w  = (wid >> 1) * 16;
    const int own  = tx >> 5;            // owner index within a chunk (0..7)
    const int s32  = tx & 31;

    const float* Gx  = lstm ? Gvf   : Gpi;
    const float* Whh = lstm ? Whhvf : Whhpi;
    const float* h0  = lstm ? h0vf  : h0pi;
    const float* c0  = lstm ? c0vf  : c0pi;
    bf16* Yh = lstm ? Yvh : Yph;
    bf16* Yl = lstm ? Yvl : Ypl;
    bf16* hhb = hhg + lstm * 2 * BB * HH;
    bf16* hlb = hlg + lstm * 2 * BB * HH;

    const uint32_t sb = smem_u32(sm8);
    const uint32_t shh[2] = { sb + OFF_HH0, sb + OFF_HH1 };
    const uint32_t shl[2] = { sb + OFF_HL0, sb + OFF_HL1 };

    const unsigned base = g_hflag[ct];   // monotonic epoch base (all threads, own flag)

    // load + split Whh slice
    for (int s = 0; s < 128; s++) {
        int idx = tx + s * 256;
        int j = idx >> 9, k = idx & 511;
        int gc = ((j >> 4) << 9) + hc0 + (j & 15);
        float w = Whh[(size_t)gc * HH + k];
        bf16 hi = __float2bfloat16_rn(w);
        sWh[j * WPAD + k] = hi;
        sWl[j * WPAD + k] = __float2bfloat16_rn(w - __bfloat162float(hi));
    }
    // init c and h0 (ping 0, pre-masked, bf16 split)
    for (int s = 0; s < 4; s++) {
        int idx = tx + s * 256;
        int br = idx >> 4, q = idx & 15;
        int b = b0 + br;
        sc[br * 16 + q] = c0[b * HH + hc0 + q];
        float m0 = 1.0f - starts[b * TT];
        float v = h0[b * HH + hc0 + q] * m0;
        bf16 hi = __float2bfloat16_rn(v);
        hhb[b * HH + hc0 + q] = hi;
        hlb[b * HH + hc0 + q] = __float2bfloat16_rn(v - __bfloat162float(hi));
    }
    __threadfence();
    __syncthreads();
    if (tx == 0) g_hflag[ct] = base + 1;

    // staging slot geometry (per thread, fixed): 8 granules, all from owner `own`
    int strow[8], sthalf[8], stm[8];
#pragma unroll
    for (int i = 0; i < 8; i++) {
        int slot = s32 + 32 * i;
        strow[i]  = slot >> 2;
        sthalf[i] = (slot >> 1) & 1;
        stm[i]    = slot & 1;
    }

    const int ebr = tx >> 2;
    const int ekb = (tx & 3) << 2;
    const int eb  = b0 + ebr;

    for (int t = 0; t < TT; t++) {
        const int cur = t & 1;
        const bf16* hcH = hhb + cur * BB * HH;
        const bf16* hcL = hlb + cur * BB * HH;
        const unsigned tgt = base + (unsigned)t + 1u;

        // per-step prefetch: G slices + masks (registers)
        const size_t grow = ((size_t)eb * TT + t) * G4 + hc0 + ekb;
        const float4 pgi = *(const float4*)(Gx + grow);
        const float4 pgf = *(const float4*)(Gx + grow + 512);
        const float4 pgg = *(const float4*)(Gx + grow + 1024);
        const float4 pgo = *(const float4*)(Gx + grow + 1536);
        const float mcur = 1.0f - starts[(size_t)eb * TT + t];
        const float mnxt = (t + 1 < TT) ? (1.0f - starts[(size_t)eb * TT + t + 1]) : 1.0f;

        // stage chunks 0,1 (poll owner flag, then issue own granules — no CTA sync)
#pragma unroll
        for (int c = 0; c < 2; c++) {
            while (g_hflag[gbase + 8 * c + own] < tgt) { }
            const uint32_t dh = shh[c & 1], dl = shl[c & 1];
#pragma unroll
            for (int i = 0; i < 8; i++) {
                uint32_t doff = (uint32_t)strow[i] * (RPAD * 2) + (uint32_t)own * 32 + (uint32_t)sthalf[i] * 16;
                size_t  soff = (size_t)(b0 + strow[i]) * 512 + c * 128 + own * 16 + sthalf[i] * 8;
                if (stm[i]) CP16(dl + doff, hcL + soff);
                else        CP16(dh + doff, hcH + soff);
            }
            CP_COMMIT();
        }

        float acc[2][2][4];
#pragma unroll
        for (int tm = 0; tm < 2; tm++)
#pragma unroll
            for (int tn = 0; tn < 2; tn++)
#pragma unroll
                for (int q = 0; q < 4; q++) acc[tm][tn][q] = 0.0f;

#pragma unroll 1
        for (int c = 0; c < 4; c++) {
            const int buf = c & 1;
            if (c < 2) { CP_WAIT1(); } else { CP_WAIT0(); }
            __syncthreads();
            const bf16* Sh = (const bf16*)(sm8 + (buf ? OFF_HH1 : OFF_HH0));
            const bf16* Sl = (const bf16*)(sm8 + (buf ? OFF_HL1 : OFF_HL0));
#pragma unroll
            for (int k16 = 0; k16 < 128; k16 += 16) {
                uint32_t ah[2][4], al[2][4];
#pragma unroll
                for (int tm = 0; tm < 2; tm++) {
                    const bf16* p = Sh + (m0w + tm * 16 + g) * RPAD + k16 + 2 * tig;
                    ah[tm][0] = *(const uint32_t*)(p);
                    ah[tm][1] = *(const uint32_t*)(p + 8 * RPAD);
                    ah[tm][2] = *(const uint32_t*)(p + 8);
                    ah[tm][3] = *(const uint32_t*)(p + 8 * RPAD + 8);
                    const bf16* q = Sl + (m0w + tm * 16 + g) * RPAD + k16 + 2 * tig;
                    al[tm][0] = *(const uint32_t*)(q);
                    al[tm][1] = *(const uint32_t*)(q + 8 * RPAD);
                    al[tm][2] = *(const uint32_t*)(q + 8);
                    al[tm][3] = *(const uint32_t*)(q + 8 * RPAD + 8);
                }
                const int kglob = c * 128 + k16 + 2 * tig;
                uint32_t bh[2][2], bl[2][2];
#pragma unroll
                for (int tn = 0; tn < 2; tn++) {
                    const bf16* p = sWh + (n0w + tn * 8 + g) * WPAD + kglob;
                    bh[tn][0] = *(const uint32_t*)(p);
                    bh[tn][1] = *(const uint32_t*)(p + 8);
                    const bf16* q = sWl + (n0w + tn * 8 + g) * WPAD + kglob;
                    bl[tn][0] = *(const uint32_t*)(q);
                    bl[tn][1] = *(const uint32_t*)(q + 8);
                }
#pragma unroll
                for (int tm = 0; tm < 2; tm++)
#pragma unroll
                    for (int tn = 0; tn < 2; tn++) {
                        MMA16816(acc[tm][tn], ah[tm], bh[tn]);
                        MMA16816(acc[tm][tn], ah[tm], bl[tn]);
                        MMA16816(acc[tm][tn], al[tm], bh[tn]);
                    }
            }
            // stage chunk c+2 (poll + issue, no sync)
            if (c + 2 < 4) {
                const int cn = c + 2;
                while (g_hflag[gbase + 8 * cn + own] < tgt) { }
                const uint32_t dh = shh[cn & 1], dl = shl[cn & 1];
#pragma unroll
                for (int i = 0; i < 8; i++) {
                    uint32_t doff = (uint32_t)strow[i] * (RPAD * 2) + (uint32_t)own * 32 + (uint32_t)sthalf[i] * 16;
                    size_t  soff = (size_t)(b0 + strow[i]) * 512 + cn * 128 + own * 16 + sthalf[i] * 8;
                    if (stm[i]) CP16(dl + doff, hcL + soff);
                    else        CP16(dh + doff, hcH + soff);
                }
                CP_COMMIT();
            }
            __syncthreads();   // staging buffer reuse safety (compute done before overwrite next iter)
        }

        // publish gate preactivations (h-part)
#pragma unroll
        for (int tm = 0; tm < 2; tm++)
#pragma unroll
            for (int tn = 0; tn < 2; tn++) {
                int r = m0w + 16 * tm + g;
                int c0i = n0w + tn * 8 + 2 * tig;
                *(float2*)&sg[r * SGPAD + c0i]       = make_float2(acc[tm][tn][0], acc[tm][tn][1]);
                *(float2*)&sg[(r + 8) * SGPAD + c0i] = make_float2(acc[tm][tn][2], acc[tm][tn][3]);
            }
        __syncthreads();

        // elementwise update
        {
            float hn[4];
#pragma unroll
            for (int i = 0; i < 4; i++) {
                int q = ekb + i;
                float vi = sg[ebr * SGPAD + q]      + ((const float*)&pgi)[i];
                float vf = sg[ebr * SGPAD + 16 + q] + ((const float*)&pgf)[i];
                float vg = sg[ebr * SGPAD + 32 + q] + ((const float*)&pgg)[i];
                float vo = sg[ebr * SGPAD + 48 + q] + ((const float*)&pgo)[i];
                float cc = sc[ebr * 16 + q] * mcur;
                float cn = sigf(vf) * cc + sigf(vi) * tanhf(vg);
                hn[i] = sigf(vo) * tanhf(cn);
                sc[ebr * 16 + q] = cn;
            }
            // next-step h (pre-masked) or final-h out
            if (t + 1 < TT) {
                bf16* hnH = hhb + ((t + 1) & 1) * BB * HH;
                bf16* hnL = hlb + ((t + 1) & 1) * BB * HH;
                size_t ho = (size_t)eb * HH + hc0 + ekb;
                __nv_bfloat162 h01, h23, l01, l23;
                float v0 = hn[0] * mnxt, v1 = hn[1] * mnxt, v2 = hn[2] * mnxt, v3 = hn[3] * mnxt;
                h01.x = __float2bfloat16_rn(v0); h01.y = __float2bfloat16_rn(v1);
                h23.x = __float2bfloat16_rn(v2); h23.y = __float2bfloat16_rn(v3);
                l01.x = __float2bfloat16_rn(v0 - __bfloat162float(h01.x));
                l01.y = __float2bfloat16_rn(v1 - __bfloat162float(h01.y));
                l23.x = __float2bfloat16_rn(v2 - __bfloat162float(h23.x));
                l23.y = __float2bfloat16_rn(v3 - __bfloat162float(h23.y));
                *(__nv_bfloat162*)(hnH + ho)     = h01;
                *(__nv_bfloat162*)(hnH + ho + 2) = h23;
                *(__nv_bfloat162*)(hnL + ho)     = l01;
                *(__nv_bfloat162*)(hnL + ho + 2) = l23;
            } else {
                float* oh = out + (size_t)3 * NR + (size_t)lstm * 2 * NR;
#pragma unroll
                for (int i = 0; i < 4; i++)
                    oh[eb * HH + hc0 + ekb + i] = hn[i];
            }
            // Y (unmasked) bf16 split
            {
                size_t yo = ((size_t)eb * TT + t) * HH + hc0 + ekb;
                __nv_bfloat162 h01, h23, l01, l23;
                h01.x = __float2bfloat16_rn(hn[0]); h01.y = __float2bfloat16_rn(hn[1]);
                h23.x = __float2bfloat16_rn(hn[2]); h23.y = __float2bfloat16_rn(hn[3]);
                l01.x = __float2bfloat16_rn(hn[0] - __bfloat162float(h01.x));
                l01.y = __float2bfloat16_rn(hn[1] - __bfloat162float(h01.y));
                l23.x = __float2bfloat16_rn(hn[2] - __bfloat162float(h23.x));
                l23.y = __float2bfloat16_rn(hn[3] - __bfloat162float(h23.y));
                *(__nv_bfloat162*)(Yh + yo)     = h01;
                *(__nv_bfloat162*)(Yh + yo + 2) = h23;
                *(__nv_bfloat162*)(Yl + yo)     = l01;
                *(__nv_bfloat162*)(Yl + yo + 2) = l23;
            }
        }
        __threadfence();
        __syncthreads();
        if (tx == 0) g_hflag[ct] = base + (unsigned)t + 2u;
    }

    // final c -> out
    float* oc = out + (size_t)3 * NR + (size_t)lstm * 2 * NR + NR;
    for (int s = 0; s < 4; s++) {
        int idx = tx + s * 256;
        int br = idx >> 4, q = idx & 15;
        oc[(b0 + br) * HH + hc0 + q] = sc[br * 16 + q];
    }
}

// ---------------- heads ----------------
__global__ __launch_bounds__(128) void head_kernel(
    const float* __restrict__ Zpi, const float* __restrict__ Zvf,
    const float* __restrict__ aw, const float* __restrict__ ab,
    const float* __restrict__ cw, const float* __restrict__ cb,
    float* __restrict__ out)
{
    __shared__ float sx[512];
    __shared__ float slog[32];
    __shared__ float sval[4];
    const int n  = blockIdx.x;
    const int tx = threadIdx.x;

    ((float4*)sx)[tx] = ((const float4*)(Zpi + (size_t)n * 512))[tx];

    float4 xv = ((const float4*)(Zvf + (size_t)n * 512))[tx];
    float4 wv = ((const float4*)cw)[tx];
    float v = xv.x * wv.x + xv.y * wv.y + xv.z * wv.z + xv.w * wv.w;
#pragma unroll
    for (int off = 16; off; off >>= 1) v += __shfl_xor_sync(0xffffffffu, v, off);
    if ((tx & 31) == 0) sval[tx >> 5] = v;
    __syncthreads();

    const int l = tx >> 2;
    const int part = tx & 3;
    const float* wl = aw + l * 512 + part * 128;
    const float* xl = sx + part * 128;
    float s = 0.0f;
#pragma unroll 8
    for (int k4 = 0; k4 < 32; k4++) {
        float4 a = ((const float4*)xl)[k4];
        float4 w = ((const float4*)wl)[k4];
        s += a.x * w.x + a.y * w.y + a.z * w.z + a.w * w.w;
    }
    s += __shfl_xor_sync(0xffffffffu, s, 1);
    s += __shfl_xor_sync(0xffffffffu, s, 2);
    if (part == 0) slog[l] = s + ab[l];
    __syncthreads();

    if (tx < 32) {
        float lv = slog[tx];
        float m = lv; int mi = tx;
#pragma unroll
        for (int off = 16; off; off >>= 1) {
            float om = __shfl_xor_sync(0xffffffffu, m, off);
            int   oi = __shfl_xor_sync(0xffffffffu, mi, off);
            if (om > m || (om == m && oi < mi)) { m = om; mi = oi; }
        }
        float e = __expf(lv - m);
#pragma unroll
        for (int off = 16; off; off >>= 1) e += __shfl_xor_sync(0xffffffffu, e, off);
        if (tx == 0) {
            out[n] = (float)mi;
            out[(size_t)NR + n] = sval[0] + sval[1] + sval[2] + sval[3] + cb[0];
            out[(size_t)2 * NR + n] = -__logf(e);
        }
    }
}

// ---------------- launch ----------------
extern "C" void kernel_launch(void* const* d_in, const int* in_sizes, int n_in,
                              void* d_out, int out_size)
{
    const float* features = (const float*)d_in[0];
    const float* starts   = (const float*)d_in[1];
    const float* h0pi = (const float*)d_in[2];
    const float* c0pi = (const float*)d_in[3];
    const float* h0vf = (const float*)d_in[4];
    const float* c0vf = (const float*)d_in[5];
    const float* Wihpi = (const float*)d_in[6];
    const float* Whhpi = (const float*)d_in[7];
    const float* bihpi = (const float*)d_in[8];
    const float* bhhpi = (const float*)d_in[9];
    const float* Wihvf = (const float*)d_in[10];
    const float* Whhvf = (const float*)d_in[11];
    const float* bihvf = (const float*)d_in[12];
    const float* bhhvf = (const float*)d_in[13];
    const float* polw1 = (const float*)d_in[14];
    const float* polb1 = (const float*)d_in[15];
    const float* polw2 = (const float*)d_in[16];
    const float* polb2 = (const float*)d_in[17];
    const float* valw1 = (const float*)d_in[18];
    const float* valb1 = (const float*)d_in[19];
    const float* valw2 = (const float*)d_in[20];
    const float* valb2 = (const float*)d_in[21];
    const float* aw = (const float*)d_in[22];
    const float* ab = (const float*)d_in[23];
    const float* cw = (const float*)d_in[24];
    const float* cb = (const float*)d_in[25];

    float *Gpi, *Gvf, *Z2pi, *Z2vf;
    cudaGetSymbolAddress((void**)&Gpi,  g_Gpi);
    cudaGetSymbolAddress((void**)&Gvf,  g_Gvf);
    cudaGetSymbolAddress((void**)&Z2pi, g_Z2pi);
    cudaGetSymbolAddress((void**)&Z2vf, g_Z2vf);
    bf16 *fh, *fl, *yph, *ypl, *yvh, *yvl, *z1ph, *z1pl, *z1vh, *z1vl, *wh, *wlp, *hh, *hl;
    cudaGetSymbolAddress((void**)&fh,  g_feat_h);
    cudaGetSymbolAddress((void**)&fl,  g_feat_l);
    cudaGetSymbolAddress((void**)&yph, g_ypi_h);
    cudaGetSymbolAddress((void**)&ypl, g_ypi_l);
    cudaGetSymbolAddress((void**)&yvh, g_yvf_h);
    cudaGetSymbolAddress((void**)&yvl, g_yvf_l);
    cudaGetSymbolAddress((void**)&z1ph, g_z1p_h);
    cudaGetSymbolAddress((void**)&z1pl, g_z1p_l);
    cudaGetSymbolAddress((void**)&z1vh, g_z1v_h);
    cudaGetSymbolAddress((void**)&z1vl, g_z1v_l);
    cudaGetSymbolAddress((void**)&wh,  g_w_h);
    cudaGetSymbolAddress((void**)&wlp, g_w_l);
    cudaGetSymbolAddress((void**)&hh,  g_hh);
    cudaGetSymbolAddress((void**)&hl,  g_hl);
    float* out = (float*)d_out;

    size_t tg_smem = (size_t)2 * STGB * sizeof(bf16);
    cudaFuncSetAttribute((const void*)tgemm, cudaFuncAttributeMaxDynamicSharedMemorySize, (int)tg_smem);
    cudaFuncSetAttribute((const void*)lstm_recur, cudaFuncAttributeMaxDynamicSharedMemorySize, LSTM_SMEM);

    // converts: features + weights
    cvt_pair<<<2048, 256>>>(features, fh, fl, (size_t)NR * DD / 4);
    cvt_pair<<<256, 256>>>(Wihpi, wh + WOFF_IHPI, wlp + WOFF_IHPI, (size_t)G4 * DD / 4);
    cvt_pair<<<256, 256>>>(Wihvf, wh + WOFF_IHVF, wlp + WOFF_IHVF, (size_t)G4 * DD / 4);
    cvt_pair<<<128, 256>>>(polw1, wh + WOFF_PW1, wlp + WOFF_PW1, (size_t)HH * HH / 4);
    cvt_pair<<<128, 256>>>(polw2, wh + WOFF_PW2, wlp + WOFF_PW2, (size_t)HH * HH / 4);
    cvt_pair<<<128, 256>>>(valw1, wh + WOFF_VW1, wlp + WOFF_VW1, (size_t)HH * HH / 4);
    cvt_pair<<<128, 256>>>(valw2, wh + WOFF_VW2, wlp + WOFF_VW2, (size_t)HH * HH / 4);

    // input GEMMs: G = X @ Wih^T + bih + bhh (fp32 out)
    tgemm<<<dim3(G4 / 128, NR / 128), 256, tg_smem>>>(fh, fl, wh + WOFF_IHPI, wlp + WOFF_IHPI,
                                                      bihpi, bhhpi, Gpi, nullptr, nullptr, G4, 0);
    tgemm<<<dim3(G4 / 128, NR / 128), 256, tg_smem>>>(fh, fl, wh + WOFF_IHVF, wlp + WOFF_IHVF,
                                                      bihvf, bhhvf, Gvf, nullptr, nullptr, G4, 0);

    // recurrence (flag-pipelined, no grid barrier)
    lstm_recur<<<128, 256, LSTM_SMEM>>>(Gpi, Gvf, starts, h0pi, c0pi, h0vf, c0vf,
                                        Whhpi, Whhvf, yph, ypl, yvh, yvl, hh, hl, out);

    // MLP layer 1 (bf16-split out, relu)
    tgemm<<<dim3(HH / 128, NR / 128), 256, tg_smem>>>(yph, ypl, wh + WOFF_PW1, wlp + WOFF_PW1,
                                                      polb1, nullptr, nullptr, z1ph, z1pl, HH, 1);
    tgemm<<<dim3(HH / 128, NR / 128), 256, tg_smem>>>(yvh, yvl, wh + WOFF_VW1, wlp + WOFF_VW1,
                                                      valb1, nullptr, nullptr, z1vh, z1vl, HH, 1);

    // MLP layer 2 (fp32 out)
    tgemm<<<dim3(HH / 128, NR / 128), 256, tg_smem>>>(z1ph, z1pl, wh + WOFF_PW2, wlp + WOFF_PW2,
                                                      polb2, nullptr, Z2pi, nullptr, nullptr, HH, 0);
    tgemm<<<dim3(HH / 128, NR / 128), 256, tg_smem>>>(z1vh, z1vl, wh + WOFF_VW2, wlp + WOFF_VW2,
                                                      valb2, nullptr, Z2vf, nullptr, nullptr, HH, 0);

    // heads
    head_kernel<<<NR, 128>>>(Z2pi, Z2vf, aw, ab, cw, cb, out);
}

// round 9
// speedup vs baseline: 1.0386x; 1.0386x over previous
#include <cuda_runtime.h>
#include <cuda_bf16.h>
#include <math.h>
#include <stdint.h>

// Problem constants
#define BB 128
#define TT 512
#define DD 512
#define HH 512
#define G4 2048
#define NR (BB*TT)
#define AA 32

typedef __nv_bfloat16 bf16;

// ---------------- scratch (device globals) ----------------
__device__ float g_Gpi[(size_t)NR * G4];
__device__ float g_Gvf[(size_t)NR * G4];
__device__ float g_Z2pi[(size_t)NR * HH];
__device__ float g_Z2vf[(size_t)NR * HH];
__device__ unsigned g_bar_count4[4];
__device__ unsigned g_bar_gen4[4];

// bf16 hi/lo pairs
__device__ __align__(16) bf16 g_feat_h[(size_t)NR * DD];
__device__ __align__(16) bf16 g_feat_l[(size_t)NR * DD];
__device__ __align__(16) bf16 g_ypi_h[(size_t)NR * HH];
__device__ __align__(16) bf16 g_ypi_l[(size_t)NR * HH];
__device__ __align__(16) bf16 g_yvf_h[(size_t)NR * HH];
__device__ __align__(16) bf16 g_yvf_l[(size_t)NR * HH];
__device__ __align__(16) bf16 g_z1p_h[(size_t)NR * HH];
__device__ __align__(16) bf16 g_z1p_l[(size_t)NR * HH];
__device__ __align__(16) bf16 g_z1v_h[(size_t)NR * HH];
__device__ __align__(16) bf16 g_z1v_l[(size_t)NR * HH];
// h ping-pong: [lstm][pingpong][128][512], bf16 hi/lo (pre-masked for the consuming step)
__device__ __align__(16) bf16 g_hh[2 * 2 * BB * HH];
__device__ __align__(16) bf16 g_hl[2 * 2 * BB * HH];
// weights blob
#define WOFF_IHPI 0
#define WOFF_IHVF 1048576
#define WOFF_PW1  2097152
#define WOFF_PW2  2359296
#define WOFF_VW1  2621440
#define WOFF_VW2  2883584
#define WTOT      3145728
__device__ __align__(16) bf16 g_w_h[WTOT];
__device__ __align__(16) bf16 g_w_l[WTOT];

__device__ __forceinline__ float sigf(float x) {
    return __fdividef(1.0f, 1.0f + __expf(-x));
}
__device__ __forceinline__ float ftanh(float x) {
    float e = __expf(2.0f * x);
    return 1.0f - __fdividef(2.0f, e + 1.0f);
}

// ---------------- PTX helpers ----------------
#define CP16(d, s) asm volatile("cp.async.cg.shared.global [%0], [%1], 16;" :: "r"(d), "l"(s) : "memory")
#define CP_COMMIT() asm volatile("cp.async.commit_group;" ::: "memory")
#define CP_WAIT0()  asm volatile("cp.async.wait_group 0;" ::: "memory")
#define CP_WAIT1()  asm volatile("cp.async.wait_group 1;" ::: "memory")

__device__ __forceinline__ uint32_t smem_u32(const void* p) {
    uint32_t a;
    asm("{ .reg .u64 t; cvta.to.shared.u64 t, %1; cvt.u32.u64 %0, t; }" : "=r"(a) : "l"(p));
    return a;
}

#define MMA16816(c, a, b) \
    asm volatile("mma.sync.aligned.m16n8k16.row.col.f32.bf16.bf16.f32 " \
        "{%0,%1,%2,%3}, {%4,%5,%6,%7}, {%8,%9}, {%0,%1,%2,%3};" \
        : "+f"((c)[0]), "+f"((c)[1]), "+f"((c)[2]), "+f"((c)[3]) \
        : "r"((a)[0]), "r"((a)[1]), "r"((a)[2]), "r"((a)[3]), "r"((b)[0]), "r"((b)[1]))

// ---------------- fp32 -> bf16 hi/lo converters ----------------
__device__ __forceinline__ void cvt_one(const float* __restrict__ x,
                                        bf16* __restrict__ hi, bf16* __restrict__ lo, size_t i)
{
    float4 v = ((const float4*)x)[i];
    bf16 h0 = __float2bfloat16_rn(v.x), h1 = __float2bfloat16_rn(v.y);
    bf16 h2 = __float2bfloat16_rn(v.z), h3 = __float2bfloat16_rn(v.w);
    bf16 l0 = __float2bfloat16_rn(v.x - __bfloat162float(h0));
    bf16 l1 = __float2bfloat16_rn(v.y - __bfloat162float(h1));
    bf16 l2 = __float2bfloat16_rn(v.z - __bfloat162float(h2));
    bf16 l3 = __float2bfloat16_rn(v.w - __bfloat162float(h3));
    __nv_bfloat162 hp0; hp0.x = h0; hp0.y = h1;
    __nv_bfloat162 hp1; hp1.x = h2; hp1.y = h3;
    __nv_bfloat162 lp0; lp0.x = l0; lp0.y = l1;
    __nv_bfloat162 lp1; lp1.x = l2; lp1.y = l3;
    ((__nv_bfloat162*)hi)[2 * i]     = hp0;
    ((__nv_bfloat162*)hi)[2 * i + 1] = hp1;
    ((__nv_bfloat162*)lo)[2 * i]     = lp0;
    ((__nv_bfloat162*)lo)[2 * i + 1] = lp1;
}

__global__ __launch_bounds__(256) void cvt_pair(const float* __restrict__ x,
                                                bf16* __restrict__ hi, bf16* __restrict__ lo, size_t n4)
{
    for (size_t i = blockIdx.x * blockDim.x + threadIdx.x; i < n4; i += (size_t)gridDim.x * blockDim.x)
        cvt_one(x, hi, lo, i);
}

// convert 3 matrices in one launch (keeps launch count low so lstm_recur = launch #5 for ncu -s 5)
__global__ __launch_bounds__(256) void cvt3(
    const float* __restrict__ x0, bf16* __restrict__ h0, bf16* __restrict__ l0, size_t n0,
    const float* __restrict__ x1, bf16* __restrict__ h1, bf16* __restrict__ l1, size_t n1,
    const float* __restrict__ x2, bf16* __restrict__ h2, bf16* __restrict__ l2, size_t n2)
{
    size_t tot = n0 + n1 + n2;
    for (size_t i = blockIdx.x * blockDim.x + threadIdx.x; i < tot; i += (size_t)gridDim.x * blockDim.x) {
        if (i < n0) cvt_one(x0, h0, l0, i);
        else if (i < n0 + n1) cvt_one(x1, h1, l1, i - n0);
        else cvt_one(x2, h2, l2, i - n0 - n1);
    }
}

// ---------------- HMMA bf16-split GEMM (unchanged, proven) ----------------
#define KSTG 32
#define ROWP 40
#define MATB (128 * ROWP)
#define STGB (4 * MATB)
__global__ __launch_bounds__(256, 1) void tgemm(
    const bf16* __restrict__ Ah, const bf16* __restrict__ Al,
    const bf16* __restrict__ Wh, const bf16* __restrict__ Wl,
    const float* __restrict__ b1, const float* __restrict__ b2,
    float* __restrict__ C, bf16* __restrict__ Ch, bf16* __restrict__ Cl,
    int N, int relu)
{
    extern __shared__ bf16 smbf[];
    const int tid  = threadIdx.x;
    const int wid  = tid >> 5, lane = tid & 31;
    const int g    = lane >> 2, tig = lane & 3;
    const int m0   = (wid & 3) * 32;
    const int n0   = (wid >> 2) * 64;
    const size_t arow0 = (size_t)blockIdx.y * 128;
    const size_t brow0 = (size_t)blockIdx.x * 128;

    const int lmat = tid >> 6, t64 = tid & 63;
    const bf16* gsrc;
    if      (lmat == 0) gsrc = Ah + arow0 * 512;
    else if (lmat == 1) gsrc = Al + arow0 * 512;
    else if (lmat == 2) gsrc = Wh + brow0 * 512;
    else                gsrc = Wl + brow0 * 512;
    const uint32_t sbase = smem_u32(smbf);
    const uint32_t sdstm = sbase + (uint32_t)lmat * (MATB * 2);

    float acc[2][8][4];
#pragma unroll
    for (int i = 0; i < 2; i++)
#pragma unroll
        for (int j = 0; j < 8; j++)
#pragma unroll
            for (int q = 0; q < 4; q++) acc[i][j][q] = 0.0f;

#pragma unroll
    for (int s = 0; s < 2; s++) {
        const uint32_t db = sdstm + (uint32_t)s * (STGB * 2);
        const int k0 = s * KSTG;
#pragma unroll
        for (int i = 0; i < 8; i++) {
            int idx = i * 64 + t64;
            int row = idx >> 2, gg = idx & 3;
            CP16(db + (uint32_t)row * (ROWP * 2) + (uint32_t)gg * 16,
                 gsrc + (size_t)row * 512 + k0 + gg * 8);
        }
        CP_COMMIT();
    }

    const int NSTG = 512 / KSTG;
#pragma unroll 1
    for (int c = 0; c < NSTG; c++) {
        if (c < NSTG - 2) { CP_WAIT1(); } else { CP_WAIT0(); }
        __syncthreads();
        const bf16* S   = smbf + (size_t)(c & 1) * STGB;
        const bf16* sAh = S;
        const bf16* sAl = S + MATB;
        const bf16* sWh = S + 2 * MATB;
        const bf16* sWl = S + 3 * MATB;
#pragma unroll
        for (int kk = 0; kk < KSTG; kk += 16) {
            uint32_t ah[2][4], al[2][4];
#pragma unroll
            for (int tm = 0; tm < 2; tm++) {
                const bf16* p = sAh + (m0 + tm * 16 + g) * ROWP + kk + 2 * tig;
                ah[tm][0] = *(const uint32_t*)(p);
                ah[tm][1] = *(const uint32_t*)(p + 8 * ROWP);
                ah[tm][2] = *(const uint32_t*)(p + 8);
                ah[tm][3] = *(const uint32_t*)(p + 8 * ROWP + 8);
                const bf16* q = sAl + (m0 + tm * 16 + g) * ROWP + kk + 2 * tig;
                al[tm][0] = *(const uint32_t*)(q);
                al[tm][1] = *(const uint32_t*)(q + 8 * ROWP);
                al[tm][2] = *(const uint32_t*)(q + 8);
                al[tm][3] = *(const uint32_t*)(q + 8 * ROWP + 8);
            }
            uint32_t bh[8][2], bl[8][2];
#pragma unroll
            for (int tn = 0; tn < 8; tn++) {
                const bf16* p = sWh + (n0 + tn * 8 + g) * ROWP + kk + 2 * tig;
                bh[tn][0] = *(const uint32_t*)(p);
                bh[tn][1] = *(const uint32_t*)(p + 8);
                const bf16* q = sWl + (n0 + tn * 8 + g) * ROWP + kk + 2 * tig;
                bl[tn][0] = *(const uint32_t*)(q);
                bl[tn][1] = *(const uint32_t*)(q + 8);
            }
#pragma unroll
            for (int tm = 0; tm < 2; tm++)
#pragma unroll
                for (int tn = 0; tn < 8; tn++) {
                    MMA16816(acc[tm][tn], ah[tm], bh[tn]);
                    MMA16816(acc[tm][tn], ah[tm], bl[tn]);
                    MMA16816(acc[tm][tn], al[tm], bh[tn]);
                }
        }
        __syncthreads();
        if (c + 2 < NSTG) {
            const uint32_t db = sdstm + (uint32_t)(c & 1) * (STGB * 2);
            const int k0 = (c + 2) * KSTG;
#pragma unroll
            for (int i = 0; i < 8; i++) {
                int idx = i * 64 + t64;
                int row = idx >> 2, gg = idx & 3;
                CP16(db + (uint32_t)row * (ROWP * 2) + (uint32_t)gg * 16,
                     gsrc + (size_t)row * 512 + k0 + gg * 8);
            }
            CP_COMMIT();
        }
    }

#pragma unroll
    for (int tn = 0; tn < 8; tn++) {
        int cc = (int)brow0 + n0 + tn * 8 + 2 * tig;
        float bv0 = b1[cc]     + (b2 ? b2[cc]     : 0.0f);
        float bv1 = b1[cc + 1] + (b2 ? b2[cc + 1] : 0.0f);
#pragma unroll
        for (int tm = 0; tm < 2; tm++) {
            size_t r0 = arow0 + m0 + tm * 16 + g;
            float v[4];
            v[0] = acc[tm][tn][0] + bv0;
            v[1] = acc[tm][tn][1] + bv1;
            v[2] = acc[tm][tn][2] + bv0;
            v[3] = acc[tm][tn][3] + bv1;
            if (relu) {
#pragma unroll
                for (int q = 0; q < 4; q++) v[q] = fmaxf(v[q], 0.f);
            }
            if (Ch) {
                __nv_bfloat162 h0, h1, l0, l1;
                h0.x = __float2bfloat16_rn(v[0]); h0.y = __float2bfloat16_rn(v[1]);
                h1.x = __float2bfloat16_rn(v[2]); h1.y = __float2bfloat16_rn(v[3]);
                l0.x = __float2bfloat16_rn(v[0] - __bfloat162float(h0.x));
                l0.y = __float2bfloat16_rn(v[1] - __bfloat162float(h0.y));
                l1.x = __float2bfloat16_rn(v[2] - __bfloat162float(h1.x));
                l1.y = __float2bfloat16_rn(v[3] - __bfloat162float(h1.y));
                *(__nv_bfloat162*)(Ch + r0 * (size_t)N + cc)       = h0;
                *(__nv_bfloat162*)(Cl + r0 * (size_t)N + cc)       = l0;
                *(__nv_bfloat162*)(Ch + (r0 + 8) * (size_t)N + cc) = h1;
                *(__nv_bfloat162*)(Cl + (r0 + 8) * (size_t)N + cc) = l1;
            } else {
                *(float2*)(C + r0 * (size_t)N + cc)       = make_float2(v[0], v[1]);
                *(float2*)(C + (r0 + 8) * (size_t)N + cc) = make_float2(v[2], v[3]);
            }
        }
    }
}

// ---------------- per-group software barrier (32 CTAs per group) ----------------
__device__ __forceinline__ void grid_bar_grp(int grp, int nct) {
    __threadfence();
    __syncthreads();
    if (threadIdx.x == 0) {
        volatile unsigned* vgen = &g_bar_gen4[grp];
        unsigned g = *vgen;
        unsigned a = atomicAdd(&g_bar_count4[grp], 1u);
        if (a == (unsigned)nct - 1u) {
            g_bar_count4[grp] = 0u;
            __threadfence();
            atomicAdd(&g_bar_gen4[grp], 1u);
        } else {
            while (*vgen == g) { }
        }
        __threadfence();
    }
    __syncthreads();
}

// ---------------- persistent recurrent kernel (R6 base + dual-acc + fast tanh) ----------------
#define RPAD 72
#define WPAD 520
#define SGPAD 72
#define OFF_WH   0
#define OFF_WL   (64 * WPAD * 2)
#define OFF_HH0  (2 * 64 * WPAD * 2)
#define OFF_HH1  (OFF_HH0 + 64 * RPAD * 2)
#define OFF_HL0  (OFF_HH0 + 2 * 64 * RPAD * 2)
#define OFF_HL1  (OFF_HL0 + 64 * RPAD * 2)
#define OFF_SG   (OFF_HH0 + 4 * 64 * RPAD * 2)
#define OFF_MASK (OFF_SG + 64 * SGPAD * 4)
#define OFF_SC   (OFF_MASK + 128 * 4)
#define LSTM_SMEM (OFF_SC + 64 * 16 * 4)

__global__ __launch_bounds__(256, 1) void lstm_recur(
    const float* __restrict__ Gpi, const float* __restrict__ Gvf,
    const float* __restrict__ starts,
    const float* __restrict__ h0pi, const float* __restrict__ c0pi,
    const float* __restrict__ h0vf, const float* __restrict__ c0vf,
    const float* __restrict__ Whhpi, const float* __restrict__ Whhvf,
    bf16* __restrict__ Yph, bf16* __restrict__ Ypl,
    bf16* __restrict__ Yvh, bf16* __restrict__ Yvl,
    bf16* __restrict__ hhg, bf16* __restrict__ hlg,
    float* __restrict__ out)
{
    extern __shared__ char sm8[];
    bf16*  sWh = (bf16*)(sm8 + OFF_WH);
    bf16*  sWl = (bf16*)(sm8 + OFF_WL);
    float* sg  = (float*)(sm8 + OFF_SG);
    float* smk = (float*)(sm8 + OFF_MASK);
    float* sc  = (float*)(sm8 + OFF_SC);

    const int ct   = blockIdx.x;
    const int lstm = ct >> 6;
    const int grp  = ct >> 5;
    const int b0   = ((ct >> 5) & 1) * 64;
    const int cid  = ct & 31;
    const int hc0  = cid * 16;
    const int tx   = threadIdx.x;
    const int wid  = tx >> 5, lane = tx & 31;
    const int g    = lane >> 2, tig = lane & 3;
    const int m0w  = (wid & 1) * 32;
    const int n0w  = (wid >> 1) * 16;

    const float* Gx  = lstm ? Gvf   : Gpi;
    const float* Whh = lstm ? Whhvf : Whhpi;
    const float* h0  = lstm ? h0vf  : h0pi;
    const float* c0  = lstm ? c0vf  : c0pi;
    bf16* Yh = lstm ? Yvh : Yph;
    bf16* Yl = lstm ? Yvl : Ypl;
    bf16* hhb = hhg + lstm * 2 * BB * HH;
    bf16* hlb = hlg + lstm * 2 * BB * HH;

    const uint32_t sb = smem_u32(sm8);
    const uint32_t shh[2] = { sb + OFF_HH0, sb + OFF_HH1 };
    const uint32_t shl[2] = { sb + OFF_HL0, sb + OFF_HL1 };

    // load + split Whh slice
    for (int s = 0; s < 128; s++) {
        int idx = tx + s * 256;
        int j = idx >> 9, k = idx & 511;
        int gc = ((j >> 4) << 9) + hc0 + (j & 15);
        float w = Whh[(size_t)gc * HH + k];
        bf16 hi = __float2bfloat16_rn(w);
        sWh[j * WPAD + k] = hi;
        sWl[j * WPAD + k] = __float2bfloat16_rn(w - __bfloat162float(hi));
    }
    // init c and h0 (ping 0, pre-masked, bf16 split)
    for (int s = 0; s < 4; s++) {
        int idx = tx + s * 256;
        int br = idx >> 4, q = idx & 15;
        int b = b0 + br;
        sc[br * 16 + q] = c0[b * HH + hc0 + q];
        float m0 = 1.0f - starts[b * TT];
        float v = h0[b * HH + hc0 + q] * m0;
        bf16 hi = __float2bfloat16_rn(v);
        hhb[b * HH + hc0 + q] = hi;
        hlb[b * HH + hc0 + q] = __float2bfloat16_rn(v - __bfloat162float(hi));
    }
    grid_bar_grp(grp, 32);

    const int ebr = tx >> 2;
    const int ekb = (tx & 3) << 2;
    const int eb  = b0 + ebr;

    for (int t = 0; t < TT; t++) {
        const int cur = t & 1;
        const bf16* hcH = hhb + cur * BB * HH;
        const bf16* hcL = hlb + cur * BB * HH;

        // G prefetch for this step (hidden behind MMA loop)
        const size_t grow = ((size_t)eb * TT + t) * G4 + hc0 + ekb;
        const float4 pgi = *(const float4*)(Gx + grow);
        const float4 pgf = *(const float4*)(Gx + grow + 512);
        const float4 pgg = *(const float4*)(Gx + grow + 1024);
        const float4 pgo = *(const float4*)(Gx + grow + 1536);

        // prefetch h chunk 0 (K 0..63)
#pragma unroll
        for (int i = 0; i < 4; i++) {
            int idx = tx + i * 256;
            int m = idx >> 9;
            int g512 = idx & 511;
            int row = g512 >> 3, gg = g512 & 7;
            uint32_t so = (uint32_t)row * (RPAD * 2) + (uint32_t)gg * 16;
            size_t  go = (size_t)(b0 + row) * 512 + gg * 8;
            if (m) CP16(shl[0] + so, hcL + go);
            else   CP16(shh[0] + so, hcH + go);
        }
        CP_COMMIT();

        // masks
        if (tx < 64) smk[tx] = 1.0f - starts[(b0 + tx) * TT + t];
        else if (tx < 128) {
            int br = tx - 64;
            smk[64 + br] = (t + 1 < TT) ? (1.0f - starts[(b0 + br) * TT + t + 1]) : 1.0f;
        }

        float acc[2][2][4], accB[2][2][4];
#pragma unroll
        for (int tm = 0; tm < 2; tm++)
#pragma unroll
            for (int tn = 0; tn < 2; tn++)
#pragma unroll
                for (int q = 0; q < 4; q++) { acc[tm][tn][q] = 0.0f; accB[tm][tn][q] = 0.0f; }

#pragma unroll 1
        for (int c = 0; c < 8; c++) {
            const int buf = c & 1;
            if (c < 7) {
                const int nb = buf ^ 1;
                const int kc = (c + 1) * 64;
#pragma unroll
                for (int i = 0; i < 4; i++) {
                    int idx = tx + i * 256;
                    int m = idx >> 9;
                    int g512 = idx & 511;
                    int row = g512 >> 3, gg = g512 & 7;
                    uint32_t so = (uint32_t)row * (RPAD * 2) + (uint32_t)gg * 16;
                    size_t  go = (size_t)(b0 + row) * 512 + kc + gg * 8;
                    if (m) CP16(shl[nb] + so, hcL + go);
                    else   CP16(shh[nb] + so, hcH + go);
                }
                CP_COMMIT();
                CP_WAIT1();
            } else {
                CP_WAIT0();
            }
            __syncthreads();
            const bf16* Sh = (const bf16*)(sm8 + (buf ? OFF_HH1 : OFF_HH0));
            const bf16* Sl = (const bf16*)(sm8 + (buf ? OFF_HL1 : OFF_HL0));
#pragma unroll
            for (int k16 = 0; k16 < 64; k16 += 16) {
                uint32_t ah[2][4], al[2][4];
#pragma unroll
                for (int tm = 0; tm < 2; tm++) {
                    const bf16* p = Sh + (m0w + tm * 16 + g) * RPAD + k16 + 2 * tig;
                    ah[tm][0] = *(const uint32_t*)(p);
                    ah[tm][1] = *(const uint32_t*)(p + 8 * RPAD);
                    ah[tm][2] = *(const uint32_t*)(p + 8);
                    ah[tm][3] = *(const uint32_t*)(p + 8 * RPAD + 8);
                    const bf16* q = Sl + (m0w + tm * 16 + g) * RPAD + k16 + 2 * tig;
                    al[tm][0] = *(const uint32_t*)(q);
                    al[tm][1] = *(const uint32_t*)(q + 8 * RPAD);
                    al[tm][2] = *(const uint32_t*)(q + 8);
                    al[tm][3] = *(const uint32_t*)(q + 8 * RPAD + 8);
                }
                const int kglob = c * 64 + k16 + 2 * tig;
                uint32_t bh[2][2], bl[2][2];
#pragma unroll
                for (int tn = 0; tn < 2; tn++) {
                    const bf16* p = sWh + (n0w + tn * 8 + g) * WPAD + kglob;
                    bh[tn][0] = *(const uint32_t*)(p);
                    bh[tn][1] = *(const uint32_t*)(p + 8);
                    const bf16* q = sWl + (n0w + tn * 8 + g) * WPAD + kglob;
                    bl[tn][0] = *(const uint32_t*)(q);
                    bl[tn][1] = *(const uint32_t*)(q + 8);
                }
#pragma unroll
                for (int tm = 0; tm < 2; tm++)
#pragma unroll
                    for (int tn = 0; tn < 2; tn++) {
                        MMA16816(acc[tm][tn],  ah[tm], bh[tn]);
                        MMA16816(accB[tm][tn], ah[tm], bl[tn]);
                        MMA16816(accB[tm][tn], al[tm], bh[tn]);
                    }
            }
            __syncthreads();
        }

        // publish gate preactivations (h-part): acc + accB
#pragma unroll
        for (int tm = 0; tm < 2; tm++)
#pragma unroll
            for (int tn = 0; tn < 2; tn++) {
                int r = m0w + 16 * tm + g;
                int c0i = n0w + tn * 8 + 2 * tig;
                *(float2*)&sg[r * SGPAD + c0i] =
                    make_float2(acc[tm][tn][0] + accB[tm][tn][0], acc[tm][tn][1] + accB[tm][tn][1]);
                *(float2*)&sg[(r + 8) * SGPAD + c0i] =
                    make_float2(acc[tm][tn][2] + accB[tm][tn][2], acc[tm][tn][3] + accB[tm][tn][3]);
            }
        __syncthreads();

        // elementwise update
        {
            const float mcur = smk[ebr];
            const float mnxt = smk[64 + ebr];
            const float gi_[4] = {pgi.x, pgi.y, pgi.z, pgi.w};
            const float gf_[4] = {pgf.x, pgf.y, pgf.z, pgf.w};
            const float gg_[4] = {pgg.x, pgg.y, pgg.z, pgg.w};
            const float go_[4] = {pgo.x, pgo.y, pgo.z, pgo.w};
            float hn[4];
#pragma unroll
            for (int i = 0; i < 4; i++) {
                int q = ekb + i;
                float vi = sg[ebr * SGPAD + q]      + gi_[i];
                float vf = sg[ebr * SGPAD + 16 + q] + gf_[i];
                float vg = sg[ebr * SGPAD + 32 + q] + gg_[i];
                float vo = sg[ebr * SGPAD + 48 + q] + go_[i];
                float cc = sc[ebr * 16 + q] * mcur;
                float cn = sigf(vf) * cc + sigf(vi) * ftanh(vg);
                hn[i] = sigf(vo) * ftanh(cn);
                sc[ebr * 16 + q] = cn;
            }
            // Y (unmasked) bf16 split
            {
                size_t yo = ((size_t)eb * TT + t) * HH + hc0 + ekb;
                __nv_bfloat162 h01, h23, l01, l23;
                h01.x = __float2bfloat16_rn(hn[0]); h01.y = __float2bfloat16_rn(hn[1]);
                h23.x = __float2bfloat16_rn(hn[2]); h23.y = __float2bfloat16_rn(hn[3]);
                l01.x = __float2bfloat16_rn(hn[0] - __bfloat162float(h01.x));
                l01.y = __float2bfloat16_rn(hn[1] - __bfloat162float(h01.y));
                l23.x = __float2bfloat16_rn(hn[2] - __bfloat162float(h23.x));
                l23.y = __float2bfloat16_rn(hn[3] - __bfloat162float(h23.y));
                *(__nv_bfloat162*)(Yh + yo)     = h01;
                *(__nv_bfloat162*)(Yh + yo + 2) = h23;
                *(__nv_bfloat162*)(Yl + yo)     = l01;
                *(__nv_bfloat162*)(Yl + yo + 2) = l23;
            }
            if (t + 1 < TT) {
                bf16* hnH = hhb + ((t + 1) & 1) * BB * HH;
                bf16* hnL = hlb + ((t + 1) & 1) * BB * HH;
                size_t ho = (size_t)eb * HH + hc0 + ekb;
                __nv_bfloat162 h01, h23, l01, l23;
                float v0 = hn[0] * mnxt, v1 = hn[1] * mnxt, v2 = hn[2] * mnxt, v3 = hn[3] * mnxt;
                h01.x = __float2bfloat16_rn(v0); h01.y = __float2bfloat16_rn(v1);
                h23.x = __float2bfloat16_rn(v2); h23.y = __float2bfloat16_rn(v3);
                l01.x = __float2bfloat16_rn(v0 - __bfloat162float(h01.x));
                l01.y = __float2bfloat16_rn(v1 - __bfloat162float(h01.y));
                l23.x = __float2bfloat16_rn(v2 - __bfloat162float(h23.x));
                l23.y = __float2bfloat16_rn(v3 - __bfloat162float(h23.y));
                *(__nv_bfloat162*)(hnH + ho)     = h01;
                *(__nv_bfloat162*)(hnH + ho + 2) = h23;
                *(__nv_bfloat162*)(hnL + ho)     = l01;
                *(__nv_bfloat162*)(hnL + ho + 2) = l23;
            } else {
                float* oh = out + (size_t)3 * NR + (size_t)lstm * 2 * NR;
#pragma unroll
                for (int i = 0; i < 4; i++)
                    oh[eb * HH + hc0 + ekb + i] = hn[i];
            }
        }
        grid_bar_grp(grp, 32);
    }

    // final c -> out
    float* oc = out + (size_t)3 * NR + (size_t)lstm * 2 * NR + NR;
    for (int s = 0; s < 4; s++) {
        int idx = tx + s * 256;
        int br = idx >> 4, q = idx & 15;
        oc[(b0 + br) * HH + hc0 + q] = sc[br * 16 + q];
    }
}

// ---------------- heads ----------------
__global__ __launch_bounds__(128) void head_kernel(
    const float* __restrict__ Zpi, const float* __restrict__ Zvf,
    const float* __restrict__ aw, const float* __restrict__ ab,
    const float* __restrict__ cw, const float* __restrict__ cb,
    float* __restrict__ out)
{
    __shared__ float sx[512];
    __shared__ float slog[32];
    __shared__ float sval[4];
    const int n  = blockIdx.x;
    const int tx = threadIdx.x;

    ((float4*)sx)[tx] = ((const float4*)(Zpi + (size_t)n * 512))[tx];

    float4 xv = ((const float4*)(Zvf + (size_t)n * 512))[tx];
    float4 wv = ((const float4*)cw)[tx];
    float v = xv.x * wv.x + xv.y * wv.y + xv.z * wv.z + xv.w * wv.w;
#pragma unroll
    for (int off = 16; off; off >>= 1) v += __shfl_xor_sync(0xffffffffu, v, off);
    if ((tx & 31) == 0) sval[tx >> 5] = v;
    __syncthreads();

    const int l = tx >> 2;
    const int part = tx & 3;
    const float* wl = aw + l * 512 + part * 128;
    const float* xl = sx + part * 128;
    float s = 0.0f;
#pragma unroll 8
    for (int k4 = 0; k4 < 32; k4++) {
        float4 a = ((const float4*)xl)[k4];
        float4 w = ((const float4*)wl)[k4];
        s += a.x * w.x + a.y * w.y + a.z * w.z + a.w * w.w;
    }
    s += __shfl_xor_sync(0xffffffffu, s, 1);
    s += __shfl_xor_sync(0xffffffffu, s, 2);
    if (part == 0) slog[l] = s + ab[l];
    __syncthreads();

    if (tx < 32) {
        float lv = slog[tx];
        float m = lv; int mi = tx;
#pragma unroll
        for (int off = 16; off; off >>= 1) {
            float om = __shfl_xor_sync(0xffffffffu, m, off);
            int   oi = __shfl_xor_sync(0xffffffffu, mi, off);
            if (om > m || (om == m && oi < mi)) { m = om; mi = oi; }
        }
        float e = __expf(lv - m);
#pragma unroll
        for (int off = 16; off; off >>= 1) e += __shfl_xor_sync(0xffffffffu, e, off);
        if (tx == 0) {
            out[n] = (float)mi;
            out[(size_t)NR + n] = sval[0] + sval[1] + sval[2] + sval[3] + cb[0];
            out[(size_t)2 * NR + n] = -__logf(e);
        }
    }
}

// ---------------- launch ----------------
extern "C" void kernel_launch(void* const* d_in, const int* in_sizes, int n_in,
                              void* d_out, int out_size)
{
    const float* features = (const float*)d_in[0];
    const float* starts   = (const float*)d_in[1];
    const float* h0pi = (const float*)d_in[2];
    const float* c0pi = (const float*)d_in[3];
    const float* h0vf = (const float*)d_in[4];
    const float* c0vf = (const float*)d_in[5];
    const float* Wihpi = (const float*)d_in[6];
    const float* Whhpi = (const float*)d_in[7];
    const float* bihpi = (const float*)d_in[8];
    const float* bhhpi = (const float*)d_in[9];
    const float* Wihvf = (const float*)d_in[10];
    const float* Whhvf = (const float*)d_in[11];
    const float* bihvf = (const float*)d_in[12];
    const float* bhhvf = (const float*)d_in[13];
    const float* polw1 = (const float*)d_in[14];
    const float* polb1 = (const float*)d_in[15];
    const float* polw2 = (const float*)d_in[16];
    const float* polb2 = (const float*)d_in[17];
    const float* valw1 = (const float*)d_in[18];
    const float* valb1 = (const float*)d_in[19];
    const float* valw2 = (const float*)d_in[20];
    const float* valb2 = (const float*)d_in[21];
    const float* aw = (const float*)d_in[22];
    const float* ab = (const float*)d_in[23];
    const float* cw = (const float*)d_in[24];
    const float* cb = (const float*)d_in[25];

    float *Gpi, *Gvf, *Z2pi, *Z2vf;
    cudaGetSymbolAddress((void**)&Gpi,  g_Gpi);
    cudaGetSymbolAddress((void**)&Gvf,  g_Gvf);
    cudaGetSymbolAddress((void**)&Z2pi, g_Z2pi);
    cudaGetSymbolAddress((void**)&Z2vf, g_Z2vf);
    bf16 *fh, *fl, *yph, *ypl, *yvh, *yvl, *z1ph, *z1pl, *z1vh, *z1vl, *wh, *wlp, *hh, *hl;
    cudaGetSymbolAddress((void**)&fh,  g_feat_h);
    cudaGetSymbolAddress((void**)&fl,  g_feat_l);
    cudaGetSymbolAddress((void**)&yph, g_ypi_h);
    cudaGetSymbolAddress((void**)&ypl, g_ypi_l);
    cudaGetSymbolAddress((void**)&yvh, g_yvf_h);
    cudaGetSymbolAddress((void**)&yvl, g_yvf_l);
    cudaGetSymbolAddress((void**)&z1ph, g_z1p_h);
    cudaGetSymbolAddress((void**)&z1pl, g_z1p_l);
    cudaGetSymbolAddress((void**)&z1vh, g_z1v_h);
    cudaGetSymbolAddress((void**)&z1vl, g_z1v_l);
    cudaGetSymbolAddress((void**)&wh,  g_w_h);
    cudaGetSymbolAddress((void**)&wlp, g_w_l);
    cudaGetSymbolAddress((void**)&hh,  g_hh);
    cudaGetSymbolAddress((void**)&hl,  g_hl);
    float* out = (float*)d_out;

    size_t tg_smem = (size_t)2 * STGB * sizeof(bf16);
    cudaFuncSetAttribute((const void*)tgemm, cudaFuncAttributeMaxDynamicSharedMemorySize, (int)tg_smem);
    cudaFuncSetAttribute((const void*)lstm_recur, cudaFuncAttributeMaxDynamicSharedMemorySize, LSTM_SMEM);

    // L0: features; L1-L2: weights (3 each) — keeps lstm_recur at launch index 5 for ncu -s 5
    cvt_pair<<<2048, 256>>>(features, fh, fl, (size_t)NR * DD / 4);
    cvt3<<<512, 256>>>(Wihpi, wh + WOFF_IHPI, wlp + WOFF_IHPI, (size_t)G4 * DD / 4,
                       Wihvf, wh + WOFF_IHVF, wlp + WOFF_IHVF, (size_t)G4 * DD / 4,
                       polw1, wh + WOFF_PW1,  wlp + WOFF_PW1,  (size_t)HH * HH / 4);
    cvt3<<<256, 256>>>(polw2, wh + WOFF_PW2,  wlp + WOFF_PW2,  (size_t)HH * HH / 4,
                       valw1, wh + WOFF_VW1,  wlp + WOFF_VW1,  (size_t)HH * HH / 4,
                       valw2, wh + WOFF_VW2,  wlp + WOFF_VW2,  (size_t)HH * HH / 4);

    // L3-L4: input GEMMs
    tgemm<<<dim3(G4 / 128, NR / 128), 256, tg_smem>>>(fh, fl, wh + WOFF_IHPI, wlp + WOFF_IHPI,
                                                      bihpi, bhhpi, Gpi, nullptr, nullptr, G4, 0);
    tgemm<<<dim3(G4 / 128, NR / 128), 256, tg_smem>>>(fh, fl, wh + WOFF_IHVF, wlp + WOFF_IHVF,
                                                      bihvf, bhhvf, Gvf, nullptr, nullptr, G4, 0);

    // L5: recurrence  (ncu -s 5 -c 1 captures this launch)
    lstm_recur<<<128, 256, LSTM_SMEM>>>(Gpi, Gvf, starts, h0pi, c0pi, h0vf, c0vf,
                                        Whhpi, Whhvf, yph, ypl, yvh, yvl, hh, hl, out);

    // MLP layer 1 (bf16-split out, relu)
    tgemm<<<dim3(HH / 128, NR / 128), 256, tg_smem>>>(yph, ypl, wh + WOFF_PW1, wlp + WOFF_PW1,
                                                      polb1, nullptr, nullptr, z1ph, z1pl, HH, 1);
    tgemm<<<dim3(HH / 128, NR / 128), 256, tg_smem>>>(yvh, yvl, wh + WOFF_VW1, wlp + WOFF_VW1,
                                                      valb1, nullptr, nullptr, z1vh, z1vl, HH, 1);

    // MLP layer 2 (fp32 out)
    tgemm<<<dim3(HH / 128, NR / 128), 256, tg_smem>>>(z1ph, z1pl, wh + WOFF_PW2, wlp + WOFF_PW2,
                                                      polb2, nullptr, Z2pi, nullptr, nullptr, HH, 0);
    tgemm<<<dim3(HH / 128, NR / 128), 256, tg_smem>>>(z1vh, z1vl, wh + WOFF_VW2, wlp + WOFF_VW2,
                                                      valb2, nullptr, Z2vf, nullptr, nullptr, HH, 0);

    // heads
    head_kernel<<<NR, 128>>>(Z2pi, Z2vf, aw, ab, cw, cb, out);
}